// round 3
// baseline (speedup 1.0000x reference)
#include <cuda_runtime.h>
#include <math.h>

#define NN 100000
#define EG 400000
#define NFEAT 128
#define HID 256
#define NOUTF 128
#define ETOT (EG + NN)

// ---------------- scratch (device globals; no allocation allowed) ----------------
__device__ float g_h[(size_t)NN * HID];     // transformed features h = x @ W
__device__ float g_feat[(size_t)NN * HID];  // layer input features (post elu)
__device__ float g_als[NN * 4];
__device__ float g_ald[NN * 4];
__device__ int   g_rowptr[NN + 1];
__device__ int   g_wp[NN + 1];
__device__ int   g_col[ETOT];
__device__ int   g_is64;

// ---------------- edge dtype sniffer ----------------
// int64 edge values < 2^31 => every odd 32-bit word is 0. For int32 edge data,
// 64 consecutive odd words all zero is (1/N)^64 ~ impossible.
__global__ void detect_k(const int* __restrict__ ew) {
    int all_zero = 1;
    for (int i = 0; i < 64; i++)
        if (ew[2 * i + 1] != 0) { all_zero = 0; break; }
    g_is64 = all_zero;
}

__device__ __forceinline__ int edge_at(const int* ew, long long idx) {
    // idx in [0, 2*EG): logical element index of the edge_index buffer
    return g_is64 ? ew[2 * idx] : ew[idx];
}

// ---------------- CSR build ----------------
__global__ void zero_wp() {
    int i = blockIdx.x * blockDim.x + threadIdx.x;
    if (i <= NN) g_wp[i] = 0;
}

__global__ void hist_k(const int* __restrict__ ew) {
    int i = blockIdx.x * blockDim.x + threadIdx.x;
    if (i >= ETOT) return;
    int d = (i < EG) ? edge_at(ew, (long long)EG + i) : (i - EG);
    atomicAdd(&g_wp[d], 1);
}

__global__ void scan_k() {
    __shared__ int sm[1024];
    __shared__ int carry_s;
    if (threadIdx.x == 0) carry_s = 0;
    __syncthreads();
    for (int base = 0; base < NN; base += 1024) {
        int i = base + threadIdx.x;
        int v = (i < NN) ? g_wp[i] : 0;
        sm[threadIdx.x] = v;
        __syncthreads();
        for (int off = 1; off < 1024; off <<= 1) {
            int t = (threadIdx.x >= off) ? sm[threadIdx.x - off] : 0;
            __syncthreads();
            sm[threadIdx.x] += t;
            __syncthreads();
        }
        int exc = sm[threadIdx.x] - v + carry_s;
        if (i < NN) { g_rowptr[i] = exc; g_wp[i] = exc; }
        __syncthreads();
        if (threadIdx.x == 0) carry_s += sm[1023];
        __syncthreads();
    }
    if (threadIdx.x == 0) g_rowptr[NN] = carry_s;
}

__global__ void scatter_k(const int* __restrict__ ew) {
    int i = blockIdx.x * blockDim.x + threadIdx.x;
    if (i >= ETOT) return;
    int s, d;
    if (i < EG) {
        s = edge_at(ew, i);
        d = edge_at(ew, (long long)EG + i);
    } else {
        s = d = i - EG;
    }
    int pos = atomicAdd(&g_wp[d], 1);
    g_col[pos] = s;
}

// ---------------- GEMM: g_h[M,Nc] = A[M,K] @ B[K,Nc], fp32, 64x64x32 tiles ----------------
// A_FROM_FEAT: read A from g_feat (device global) instead of the param pointer.
template <bool A_FROM_FEAT>
__global__ void __launch_bounds__(256) gemm_k(
    const float* __restrict__ Ap, const float* __restrict__ B,
    int M, int K, int Nc)
{
    const float* __restrict__ A = A_FROM_FEAT ? (const float*)g_feat : Ap;
    __shared__ float As[32][68];
    __shared__ float Bs[32][68];
    int tid = threadIdx.x;
    int tx = tid & 15, ty = tid >> 4;
    int row0 = blockIdx.y * 64, col0 = blockIdx.x * 64;
    float acc[4][4];
#pragma unroll
    for (int i = 0; i < 4; i++)
#pragma unroll
        for (int j = 0; j < 4; j++) acc[i][j] = 0.f;

    for (int kk = 0; kk < K; kk += 32) {
        // load A tile: 64 rows x 32 cols = 512 float4, 2 per thread (stored transposed)
#pragma unroll
        for (int i = 0; i < 2; i++) {
            int f = tid + 256 * i;
            int r = f >> 3, c4 = f & 7;
            int gr = row0 + r;
            float4 v = make_float4(0.f, 0.f, 0.f, 0.f);
            if (gr < M) v = *(const float4*)(A + (size_t)gr * K + kk + c4 * 4);
            As[c4 * 4 + 0][r] = v.x;
            As[c4 * 4 + 1][r] = v.y;
            As[c4 * 4 + 2][r] = v.z;
            As[c4 * 4 + 3][r] = v.w;
        }
        // load B tile: 32 rows x 64 cols = 512 float4, 2 per thread
#pragma unroll
        for (int i = 0; i < 2; i++) {
            int f = tid + 256 * i;
            int r = f >> 4, c4 = f & 15;
            float4 v = *(const float4*)(B + (size_t)(kk + r) * Nc + col0 + c4 * 4);
            Bs[r][c4 * 4 + 0] = v.x;
            Bs[r][c4 * 4 + 1] = v.y;
            Bs[r][c4 * 4 + 2] = v.z;
            Bs[r][c4 * 4 + 3] = v.w;
        }
        __syncthreads();
#pragma unroll
        for (int k = 0; k < 32; k++) {
            float a[4], b[4];
#pragma unroll
            for (int i = 0; i < 4; i++) a[i] = As[k][ty * 4 + i];
#pragma unroll
            for (int j = 0; j < 4; j++) b[j] = Bs[k][tx * 4 + j];
#pragma unroll
            for (int i = 0; i < 4; i++)
#pragma unroll
                for (int j = 0; j < 4; j++) acc[i][j] += a[i] * b[j];
        }
        __syncthreads();
    }
#pragma unroll
    for (int i = 0; i < 4; i++) {
        int gr = row0 + ty * 4 + i;
        if (gr < M) {
#pragma unroll
            for (int j = 0; j < 4; j++)
                g_h[(size_t)gr * Nc + col0 + tx * 4 + j] = acc[i][j];
        }
    }
}

// ---------------- per-node attention scalars: al_s, al_d (reads g_h) ----------------
__global__ void al_k(const float* __restrict__ asrc,
                     const float* __restrict__ adst, int H, int C)
{
    int wid = (blockIdx.x * blockDim.x + threadIdx.x) >> 5;
    int lane = threadIdx.x & 31;
    if (wid >= NN) return;
    const float* hr = g_h + (size_t)wid * H * C;
    for (int hd = 0; hd < H; hd++) {
        float s = 0.f, d = 0.f;
        for (int c = lane; c < C; c += 32) {
            float v = hr[hd * C + c];
            s += v * asrc[hd * C + c];
            d += v * adst[hd * C + c];
        }
#pragma unroll
        for (int off = 16; off; off >>= 1) {
            s += __shfl_xor_sync(0xffffffffu, s, off);
            d += __shfl_xor_sync(0xffffffffu, d, off);
        }
        if (lane == 0) { g_als[wid * H + hd] = s; g_ald[wid * H + hd] = d; }
    }
}

// ---------------- fused softmax + aggregation + bias (+ELU), warp per dst node ----------------
// Reads g_h / g_als / g_ald / CSR. WRITE_OUT: write to param out; else to g_feat.
template <int H, int C, bool ELU, bool WRITE_OUT>
__global__ void __launch_bounds__(256) agg_k(
    const float* __restrict__ bias, float* __restrict__ outp)
{
    constexpr int HC = H * C;
    constexpr int V = HC / 128;  // float4s per lane
    int wid = (blockIdx.x * blockDim.x + threadIdx.x) >> 5;
    int lane = threadIdx.x & 31;
    if (wid >= NN) return;
    int beg = g_rowptr[wid], end = g_rowptr[wid + 1];

    float aldv = (lane < H) ? g_ald[wid * H + lane] : 0.f;

    // pass 1: per-head max of leaky_relu(al_s[src] + al_d[dst])
    float mh = -1e30f;
    for (int e = beg; e < end; e++) {
        int s = g_col[e];
        if (lane < H) {
            float ev = g_als[s * H + lane] + aldv;
            ev = ev > 0.f ? ev : 0.2f * ev;
            mh = fmaxf(mh, ev);
        }
    }

    // pass 2: denom and weighted feature sum
    float4 acc[V];
#pragma unroll
    for (int v = 0; v < V; v++) acc[v] = make_float4(0.f, 0.f, 0.f, 0.f);
    float denom = 0.f;

    for (int e = beg; e < end; e++) {
        int s = g_col[e];
        float exh = 0.f;
        if (lane < H) {
            float ev = g_als[s * H + lane] + aldv;
            ev = ev > 0.f ? ev : 0.2f * ev;
            exh = __expf(ev - mh);
            denom += exh;
        }
        const float4* hv = (const float4*)(g_h + (size_t)s * HC);
#pragma unroll
        for (int v = 0; v < V; v++) {
            int c4 = lane + 32 * v;
            int head = (4 * c4) / C;
            float a = __shfl_sync(0xffffffffu, exh, head);
            float4 xv = hv[c4];
            acc[v].x += a * xv.x;
            acc[v].y += a * xv.y;
            acc[v].z += a * xv.z;
            acc[v].w += a * xv.w;
        }
    }

    float* obase = WRITE_OUT ? outp : (float*)g_feat;
    float4* op = (float4*)(obase + (size_t)wid * HC);
#pragma unroll
    for (int v = 0; v < V; v++) {
        int c4 = lane + 32 * v;
        int head = (4 * c4) / C;
        float den = __shfl_sync(0xffffffffu, denom, head) + 1e-16f;
        float inv = 1.f / den;
        float4 b4 = ((const float4*)bias)[c4];
        float4 o;
        o.x = acc[v].x * inv + b4.x;
        o.y = acc[v].y * inv + b4.y;
        o.z = acc[v].z * inv + b4.z;
        o.w = acc[v].w * inv + b4.w;
        if (ELU) {
            o.x = o.x > 0.f ? o.x : expm1f(o.x);
            o.y = o.y > 0.f ? o.y : expm1f(o.y);
            o.z = o.z > 0.f ? o.z : expm1f(o.z);
            o.w = o.w > 0.f ? o.w : expm1f(o.w);
        }
        op[c4] = o;
    }
}

// ---------------- launch ----------------
extern "C" void kernel_launch(void* const* d_in, const int* in_sizes, int n_in,
                              void* d_out, int out_size)
{
    const float* x   = (const float*)d_in[0];
    const int*   ew  = (const int*)d_in[1];   // edge_index words (int32 or int64, sniffed)
    const float* W0  = (const float*)d_in[2];
    const float* as0 = (const float*)d_in[3];
    const float* ad0 = (const float*)d_in[4];
    const float* b0  = (const float*)d_in[5];
    const float* W1  = (const float*)d_in[6];
    const float* as1 = (const float*)d_in[7];
    const float* ad1 = (const float*)d_in[8];
    const float* b1  = (const float*)d_in[9];
    const float* W2  = (const float*)d_in[10];
    const float* as2 = (const float*)d_in[11];
    const float* ad2 = (const float*)d_in[12];
    const float* b2  = (const float*)d_in[13];
    float* out = (float*)d_out;

    // CSR build (shared across all three layers)
    detect_k<<<1, 1>>>(ew);
    zero_wp<<<(NN + 256) / 256, 256>>>();
    hist_k<<<(ETOT + 255) / 256, 256>>>(ew);
    scan_k<<<1, 1024>>>();
    scatter_k<<<(ETOT + 255) / 256, 256>>>(ew);

    int warp_blocks = (NN * 32 + 255) / 256;

    // layer 0: x[N,128] @ W0[128,256]
    {
        dim3 g(HID / 64, (NN + 63) / 64);
        gemm_k<false><<<g, 256>>>(x, W0, NN, NFEAT, HID);
        al_k<<<warp_blocks, 256>>>(as0, ad0, 4, 64);
        agg_k<4, 64, true, false><<<warp_blocks, 256>>>(b0, nullptr);
    }
    // layer 1: feat[N,256] @ W1[256,256]
    {
        dim3 g(HID / 64, (NN + 63) / 64);
        gemm_k<true><<<g, 256>>>(nullptr, W1, NN, HID, HID);
        al_k<<<warp_blocks, 256>>>(as1, ad1, 4, 64);
        agg_k<4, 64, true, false><<<warp_blocks, 256>>>(b1, nullptr);
    }
    // layer 2: feat[N,256] @ W2[256,128], H=1, no ELU, writes d_out
    {
        dim3 g(NOUTF / 64, (NN + 63) / 64);
        gemm_k<true><<<g, 256>>>(nullptr, W2, NN, HID, NOUTF);
        al_k<<<warp_blocks, 256>>>(as2, ad2, 1, 128);
        agg_k<1, 128, false, true><<<warp_blocks, 256>>>(b2, out);
    }
}

// round 4
// speedup vs baseline: 1.1555x; 1.1555x over previous
#include <cuda_runtime.h>
#include <math.h>

#define NN 100000
#define EG 400000
#define NFEAT 128
#define HID 256
#define NOUTF 128
#define ETOT (EG + NN)

// ---------------- scratch (device globals; no allocation allowed) ----------------
__device__ float g_h[(size_t)NN * HID];     // transformed features h = x @ W
__device__ float g_feat[(size_t)NN * HID];  // layer input features (post elu)
__device__ float g_als[NN * 4];
__device__ float g_ald[NN * 4];
__device__ int   g_rowptr[NN + 1];
__device__ int   g_wp[NN + 1];
__device__ int   g_col[ETOT];
__device__ int   g_is64;

// ---------------- edge dtype sniffer ----------------
__global__ void detect_k(const int* __restrict__ ew) {
    int all_zero = 1;
    for (int i = 0; i < 64; i++)
        if (ew[2 * i + 1] != 0) { all_zero = 0; break; }
    g_is64 = all_zero;
}

__device__ __forceinline__ int edge_at(const int* ew, long long idx) {
    return g_is64 ? ew[2 * idx] : ew[idx];
}

// ---------------- CSR build ----------------
__global__ void zero_wp() {
    int i = blockIdx.x * blockDim.x + threadIdx.x;
    if (i <= NN) g_wp[i] = 0;
}

__global__ void hist_k(const int* __restrict__ ew) {
    int i = blockIdx.x * blockDim.x + threadIdx.x;
    if (i >= ETOT) return;
    int d = (i < EG) ? edge_at(ew, (long long)EG + i) : (i - EG);
    atomicAdd(&g_wp[d], 1);
}

// thread-coarsened single-block scan: each thread owns a contiguous chunk
__global__ void scan_k() {
    __shared__ int ssum[1024];
    int t = threadIdx.x;
    const int CH = (NN + 1023) / 1024;   // 98
    int beg = t * CH;
    int end = beg + CH; if (end > NN) end = NN;
    if (beg > NN) beg = NN;
    int s = 0;
    for (int i = beg; i < end; i++) s += g_wp[i];
    ssum[t] = s;
    __syncthreads();
    for (int off = 1; off < 1024; off <<= 1) {
        int v = (t >= off) ? ssum[t - off] : 0;
        __syncthreads();
        ssum[t] += v;
        __syncthreads();
    }
    int run = ssum[t] - s;   // exclusive prefix at chunk start
    for (int i = beg; i < end; i++) {
        int v = g_wp[i];
        g_rowptr[i] = run;
        g_wp[i] = run;
        run += v;
    }
    if (t == 1023) g_rowptr[NN] = run;
}

__global__ void scatter_k(const int* __restrict__ ew) {
    int i = blockIdx.x * blockDim.x + threadIdx.x;
    if (i >= ETOT) return;
    int s, d;
    if (i < EG) {
        s = edge_at(ew, i);
        d = edge_at(ew, (long long)EG + i);
    } else {
        s = d = i - EG;
    }
    int pos = atomicAdd(&g_wp[d], 1);
    g_col[pos] = s;
}

// ---------------- GEMM: g_h[M,Nc] = A[M,K] @ B[K,Nc], fp32, 128x64x32 tiles ----------------
// A_FROM_FEAT: read A from g_feat. AL_FUSE: BN=64 == head width -> compute
// al_s/al_d in epilogue via 16-lane reduction (layers 0/1 only).
template <bool A_FROM_FEAT, bool AL_FUSE>
__global__ void __launch_bounds__(256) gemm_k(
    const float* __restrict__ Ap, const float* __restrict__ B,
    const float* __restrict__ asrc, const float* __restrict__ adst,
    int M, int K, int Nc)
{
    const float* __restrict__ A = A_FROM_FEAT ? (const float*)g_feat : Ap;
    __shared__ float As[32][132];   // transposed: As[k][row]
    __shared__ float Bs[32][68];
    int tid = threadIdx.x;
    int tx = tid & 15, ty = tid >> 4;
    int row0 = blockIdx.y * 128, col0 = blockIdx.x * 64;
    float acc[8][4];
#pragma unroll
    for (int i = 0; i < 8; i++)
#pragma unroll
        for (int j = 0; j < 4; j++) acc[i][j] = 0.f;

    for (int kk = 0; kk < K; kk += 32) {
        // A tile: 128 rows x 32 k = 1024 float4, 4 per thread
#pragma unroll
        for (int l = 0; l < 4; l++) {
            int f = tid + 256 * l;
            int r = f >> 3, c4 = f & 7;
            int gr = row0 + r;
            float4 v = make_float4(0.f, 0.f, 0.f, 0.f);
            if (gr < M) v = *(const float4*)(A + (size_t)gr * K + kk + c4 * 4);
            As[c4 * 4 + 0][r] = v.x;
            As[c4 * 4 + 1][r] = v.y;
            As[c4 * 4 + 2][r] = v.z;
            As[c4 * 4 + 3][r] = v.w;
        }
        // B tile: 32 k x 64 cols = 512 float4, 2 per thread
#pragma unroll
        for (int l = 0; l < 2; l++) {
            int f = tid + 256 * l;
            int r = f >> 4, c4 = f & 15;
            float4 v = *(const float4*)(B + (size_t)(kk + r) * Nc + col0 + c4 * 4);
            Bs[r][c4 * 4 + 0] = v.x;
            Bs[r][c4 * 4 + 1] = v.y;
            Bs[r][c4 * 4 + 2] = v.z;
            Bs[r][c4 * 4 + 3] = v.w;
        }
        __syncthreads();
#pragma unroll
        for (int k = 0; k < 32; k++) {
            float a[8], b[4];
#pragma unroll
            for (int i = 0; i < 8; i++) a[i] = As[k][ty * 8 + i];
#pragma unroll
            for (int j = 0; j < 4; j++) b[j] = Bs[k][tx * 4 + j];
#pragma unroll
            for (int i = 0; i < 8; i++)
#pragma unroll
                for (int j = 0; j < 4; j++) acc[i][j] += a[i] * b[j];
        }
        __syncthreads();
    }

#pragma unroll
    for (int i = 0; i < 8; i++) {
        int gr = row0 + ty * 8 + i;
        if (gr < M) {
#pragma unroll
            for (int j = 0; j < 4; j++)
                g_h[(size_t)gr * Nc + col0 + tx * 4 + j] = acc[i][j];
        }
    }

    if (AL_FUSE) {
        // block covers one full head (64 cols). Row dot-products with a_src/a_dst.
        int head = col0 >> 6;
        float wsv[4], wdv[4];
#pragma unroll
        for (int j = 0; j < 4; j++) {
            wsv[j] = asrc[col0 + tx * 4 + j];
            wdv[j] = adst[col0 + tx * 4 + j];
        }
#pragma unroll
        for (int i = 0; i < 8; i++) {
            float ps = 0.f, pd = 0.f;
#pragma unroll
            for (int j = 0; j < 4; j++) {
                ps += acc[i][j] * wsv[j];
                pd += acc[i][j] * wdv[j];
            }
#pragma unroll
            for (int off = 8; off; off >>= 1) {
                ps += __shfl_xor_sync(0xffffffffu, ps, off);
                pd += __shfl_xor_sync(0xffffffffu, pd, off);
            }
            int gr = row0 + ty * 8 + i;
            if (tx == 0 && gr < M) {
                g_als[gr * 4 + head] = ps;
                g_ald[gr * 4 + head] = pd;
            }
        }
    }
}

// ---------------- per-node attention scalars (layer 2 only, H=1, C=128) ----------------
__global__ void al_k(const float* __restrict__ asrc,
                     const float* __restrict__ adst, int H, int C)
{
    int wid = (blockIdx.x * blockDim.x + threadIdx.x) >> 5;
    int lane = threadIdx.x & 31;
    if (wid >= NN) return;
    const float* hr = g_h + (size_t)wid * H * C;
    for (int hd = 0; hd < H; hd++) {
        float s = 0.f, d = 0.f;
        for (int c = lane; c < C; c += 32) {
            float v = hr[hd * C + c];
            s += v * asrc[hd * C + c];
            d += v * adst[hd * C + c];
        }
#pragma unroll
        for (int off = 16; off; off >>= 1) {
            s += __shfl_xor_sync(0xffffffffu, s, off);
            d += __shfl_xor_sync(0xffffffffu, d, off);
        }
        if (lane == 0) { g_als[wid * H + hd] = s; g_ald[wid * H + hd] = d; }
    }
}

// ---------------- fused softmax + aggregation + bias (+ELU), warp per dst node ----------------
// Single pass: scores are O(1), so exp without max-shift is safe; differs from
// reference only through the +1e-16 epsilon (relative ~1e-16).
template <int H, int C, bool ELU, bool WRITE_OUT>
__global__ void __launch_bounds__(256) agg_k(
    const float* __restrict__ bias, float* __restrict__ outp)
{
    constexpr int HC = H * C;
    constexpr int V = HC / 128;  // float4s per lane
    int wid = (blockIdx.x * blockDim.x + threadIdx.x) >> 5;
    int lane = threadIdx.x & 31;
    if (wid >= NN) return;
    int beg = g_rowptr[wid], end = g_rowptr[wid + 1];

    float aldv = (lane < H) ? g_ald[wid * H + lane] : 0.f;

    float4 acc[V];
#pragma unroll
    for (int v = 0; v < V; v++) acc[v] = make_float4(0.f, 0.f, 0.f, 0.f);
    float denom = 0.f;

    for (int e = beg; e < end; e++) {
        int s = g_col[e];
        float exh = 0.f;
        if (lane < H) {
            float ev = g_als[s * H + lane] + aldv;
            ev = ev > 0.f ? ev : 0.2f * ev;
            exh = __expf(ev);
            denom += exh;
        }
        const float4* hv = (const float4*)(g_h + (size_t)s * HC);
#pragma unroll
        for (int v = 0; v < V; v++) {
            int c4 = lane + 32 * v;
            int head = (4 * c4) / C;
            float a = __shfl_sync(0xffffffffu, exh, head);
            float4 xv = hv[c4];
            acc[v].x += a * xv.x;
            acc[v].y += a * xv.y;
            acc[v].z += a * xv.z;
            acc[v].w += a * xv.w;
        }
    }

    float* obase = WRITE_OUT ? outp : (float*)g_feat;
    float4* op = (float4*)(obase + (size_t)wid * HC);
#pragma unroll
    for (int v = 0; v < V; v++) {
        int c4 = lane + 32 * v;
        int head = (4 * c4) / C;
        float den = __shfl_sync(0xffffffffu, denom, head) + 1e-16f;
        float inv = 1.f / den;
        float4 b4 = ((const float4*)bias)[c4];
        float4 o;
        o.x = acc[v].x * inv + b4.x;
        o.y = acc[v].y * inv + b4.y;
        o.z = acc[v].z * inv + b4.z;
        o.w = acc[v].w * inv + b4.w;
        if (ELU) {
            o.x = o.x > 0.f ? o.x : expm1f(o.x);
            o.y = o.y > 0.f ? o.y : expm1f(o.y);
            o.z = o.z > 0.f ? o.z : expm1f(o.z);
            o.w = o.w > 0.f ? o.w : expm1f(o.w);
        }
        op[c4] = o;
    }
}

// ---------------- launch ----------------
extern "C" void kernel_launch(void* const* d_in, const int* in_sizes, int n_in,
                              void* d_out, int out_size)
{
    const float* x   = (const float*)d_in[0];
    const int*   ew  = (const int*)d_in[1];
    const float* W0  = (const float*)d_in[2];
    const float* as0 = (const float*)d_in[3];
    const float* ad0 = (const float*)d_in[4];
    const float* b0  = (const float*)d_in[5];
    const float* W1  = (const float*)d_in[6];
    const float* as1 = (const float*)d_in[7];
    const float* ad1 = (const float*)d_in[8];
    const float* b1  = (const float*)d_in[9];
    const float* W2  = (const float*)d_in[10];
    const float* as2 = (const float*)d_in[11];
    const float* ad2 = (const float*)d_in[12];
    const float* b2  = (const float*)d_in[13];
    float* out = (float*)d_out;

    // CSR build (shared across all three layers)
    detect_k<<<1, 1>>>(ew);
    zero_wp<<<(NN + 256) / 256, 256>>>();
    hist_k<<<(ETOT + 255) / 256, 256>>>(ew);
    scan_k<<<1, 1024>>>();
    scatter_k<<<(ETOT + 255) / 256, 256>>>(ew);

    int warp_blocks = (NN * 32 + 255) / 256;

    // layer 0: x[N,128] @ W0[128,256]  (al fused into GEMM epilogue)
    {
        dim3 g(HID / 64, (NN + 127) / 128);
        gemm_k<false, true><<<g, 256>>>(x, W0, as0, ad0, NN, NFEAT, HID);
        agg_k<4, 64, true, false><<<warp_blocks, 256>>>(b0, nullptr);
    }
    // layer 1: feat[N,256] @ W1[256,256]  (al fused)
    {
        dim3 g(HID / 64, (NN + 127) / 128);
        gemm_k<true, true><<<g, 256>>>(nullptr, W1, as1, ad1, NN, HID, HID);
        agg_k<4, 64, true, false><<<warp_blocks, 256>>>(b1, nullptr);
    }
    // layer 2: feat[N,256] @ W2[256,128], H=1 (C=128 spans 2 blocks -> separate al_k)
    {
        dim3 g(NOUTF / 64, (NN + 127) / 128);
        gemm_k<true, false><<<g, 256>>>(nullptr, W2, nullptr, nullptr, NN, HID, NOUTF);
        al_k<<<warp_blocks, 256>>>(as2, ad2, 1, 128);
        agg_k<1, 128, false, true><<<warp_blocks, 256>>>(b2, out);
    }
}

// round 6
// speedup vs baseline: 2.1090x; 1.8252x over previous
#include <cuda_runtime.h>
#include <cuda_bf16.h>
#include <math.h>
#include <cstdint>

#define NN 100000
#define EG 400000
#define NFEAT 128
#define HID 256
#define NOUTF 128
#define ETOT (EG + NN)
#define SCB ((NN + 255) / 256)

// ---------------- scratch (device globals; no allocation allowed) ----------------
__device__ float g_h[(size_t)NN * HID];            // transformed features h (fp32)
__device__ __nv_bfloat16 g_xa_hi[(size_t)NN * NFEAT];
__device__ __nv_bfloat16 g_xa_lo[(size_t)NN * NFEAT];
__device__ __nv_bfloat16 g_fa_hi[(size_t)NN * HID];  // layer activations, split bf16
__device__ __nv_bfloat16 g_fa_lo[(size_t)NN * HID];
__device__ __nv_bfloat16 g_w0t_hi[HID * NFEAT], g_w0t_lo[HID * NFEAT];   // [N][K]
__device__ __nv_bfloat16 g_w1t_hi[HID * HID],   g_w1t_lo[HID * HID];
__device__ __nv_bfloat16 g_w2t_hi[NOUTF * HID], g_w2t_lo[NOUTF * HID];
__device__ float g_als[NN * 4];
__device__ float g_ald[NN * 4];
__device__ int   g_rowptr[NN + 1];
__device__ int   g_wp[NN + 1];
__device__ int   g_bsum[SCB + 1];
__device__ int   g_col[ETOT];
__device__ int   g_is64;

// ---------------- warp-MMA helpers (portable PTX, sm_80+) ----------------
__device__ __forceinline__ uint32_t smem_u32(const void* p) {
    uint32_t a;
    asm("{ .reg .u64 t; cvta.to.shared.u64 t, %1; cvt.u32.u64 %0, t; }" : "=r"(a) : "l"(p));
    return a;
}
__device__ __forceinline__ void ldmx4(uint32_t* r, uint32_t addr) {
    asm volatile("ldmatrix.sync.aligned.m8n8.x4.shared.b16 {%0,%1,%2,%3}, [%4];"
                 : "=r"(r[0]), "=r"(r[1]), "=r"(r[2]), "=r"(r[3]) : "r"(addr));
}
__device__ __forceinline__ void ldmx2(uint32_t* r, uint32_t addr) {
    asm volatile("ldmatrix.sync.aligned.m8n8.x2.shared.b16 {%0,%1}, [%2];"
                 : "=r"(r[0]), "=r"(r[1]) : "r"(addr));
}
__device__ __forceinline__ void mma16816(float* c, const uint32_t* a, const uint32_t* b) {
    asm volatile("mma.sync.aligned.m16n8k16.row.col.f32.bf16.bf16.f32 "
                 "{%0,%1,%2,%3}, {%4,%5,%6,%7}, {%8,%9}, {%0,%1,%2,%3};"
                 : "+f"(c[0]), "+f"(c[1]), "+f"(c[2]), "+f"(c[3])
                 : "r"(a[0]), "r"(a[1]), "r"(a[2]), "r"(a[3]), "r"(b[0]), "r"(b[1]));
}

// ---------------- edge dtype sniffer ----------------
__global__ void detect_k(const int* __restrict__ ew) {
    int all_zero = 1;
    for (int i = 0; i < 64; i++)
        if (ew[2 * i + 1] != 0) { all_zero = 0; break; }
    g_is64 = all_zero;
}
__device__ __forceinline__ int edge_at(const int* ew, long long idx) {
    return g_is64 ? ew[2 * idx] : ew[idx];
}

// ---------------- CSR build ----------------
__global__ void zero_wp() {
    int i = blockIdx.x * blockDim.x + threadIdx.x;
    if (i <= NN) g_wp[i] = 0;
}
__global__ void hist_k(const int* __restrict__ ew) {
    int i = blockIdx.x * blockDim.x + threadIdx.x;
    if (i >= ETOT) return;
    int d = (i < EG) ? edge_at(ew, (long long)EG + i) : (i - EG);
    atomicAdd(&g_wp[d], 1);
}
__global__ void part_k() {
    __shared__ int sm[256];
    int i = blockIdx.x * 256 + threadIdx.x;
    int v = (i < NN) ? g_wp[i] : 0;
    sm[threadIdx.x] = v;
    __syncthreads();
    for (int off = 128; off; off >>= 1) {
        if (threadIdx.x < off) sm[threadIdx.x] += sm[threadIdx.x + off];
        __syncthreads();
    }
    if (threadIdx.x == 0) g_bsum[blockIdx.x] = sm[0];
}
__global__ void bscan_k() {
    __shared__ int sm[512];
    int t = threadIdx.x;
    int v = (t < SCB) ? g_bsum[t] : 0;
    sm[t] = v;
    __syncthreads();
    for (int off = 1; off < 512; off <<= 1) {
        int u = (t >= off) ? sm[t - off] : 0;
        __syncthreads();
        sm[t] += u;
        __syncthreads();
    }
    if (t < SCB) g_bsum[t] = sm[t] - v;
}
__global__ void final_k() {
    __shared__ int sm[256];
    int b = blockIdx.x, t = threadIdx.x;
    int i = b * 256 + t;
    int v = (i < NN) ? g_wp[i] : 0;
    sm[t] = v;
    __syncthreads();
    for (int off = 1; off < 256; off <<= 1) {
        int u = (t >= off) ? sm[t - off] : 0;
        __syncthreads();
        sm[t] += u;
        __syncthreads();
    }
    int exc = g_bsum[b] + sm[t] - v;
    if (i < NN) { g_rowptr[i] = exc; g_wp[i] = exc; }
    if (i == NN - 1) g_rowptr[NN] = g_bsum[b] + sm[t];
}
__global__ void scatter_k(const int* __restrict__ ew) {
    int i = blockIdx.x * blockDim.x + threadIdx.x;
    if (i >= ETOT) return;
    int s, d;
    if (i < EG) { s = edge_at(ew, i); d = edge_at(ew, (long long)EG + i); }
    else { s = d = i - EG; }
    int pos = atomicAdd(&g_wp[d], 1);
    g_col[pos] = s;
}

// ---------------- split / transpose prep ----------------
__global__ void prepw_k(const float* __restrict__ W, int which, int K, int Nc) {
    int i = blockIdx.x * 256 + threadIdx.x;
    if (i >= K * Nc) return;
    int k = i / Nc, n = i % Nc;
    float v = W[i];
    __nv_bfloat16 h = __float2bfloat16(v);
    __nv_bfloat16 l = __float2bfloat16(v - __bfloat162float(h));
    size_t o = (size_t)n * K + k;
    if (which == 0)      { g_w0t_hi[o] = h; g_w0t_lo[o] = l; }
    else if (which == 1) { g_w1t_hi[o] = h; g_w1t_lo[o] = l; }
    else                 { g_w2t_hi[o] = h; g_w2t_lo[o] = l; }
}
__global__ void prepx_k(const float* __restrict__ x) {
    int i = blockIdx.x * 256 + threadIdx.x;
    if (i >= NN * NFEAT) return;
    float v = x[i];
    __nv_bfloat16 h = __float2bfloat16(v);
    g_xa_hi[i] = h;
    g_xa_lo[i] = __float2bfloat16(v - __bfloat162float(h));
}

// ---------------- split-bf16 HMMA GEMM: C[M,Nc] = A[M,K] @ Wt[Nc,K]^T ----------------
// CTA tile 128x128, 8 warps (2m x 4n), warp tile 64x32, K-chunk 64 bf16.
// Smem tiles XOR-swizzled: off(row,chunk16B) = row*128 + ((chunk ^ (row&7))<<4).
// Fused epilogue: al_s/al_d row dots via 4-lane shfl + smem atomics.
#define SM_A_HI 0
#define SM_A_LO 16384
#define SM_B_HI 32768
#define SM_B_LO 49152
#define SM_ALS  65536
#define SM_ALD  (65536 + 1024)
#define SMEM_MM (65536 + 2048)

template <int LAYER>
__global__ void __launch_bounds__(256) mm_k(const float* __restrict__ asrc,
                                            const float* __restrict__ adst)
{
    constexpr int K  = (LAYER == 0) ? NFEAT : HID;
    constexpr int Nc = (LAYER == 2) ? NOUTF : HID;
    constexpr int NCH = K / 64;

    extern __shared__ char smem[];
    uint32_t sb = smem_u32(smem);
    float* sals = (float*)(smem + SM_ALS);
    float* sald = (float*)(smem + SM_ALD);

    int tid = threadIdx.x, w = tid >> 5, lane = tid & 31;
    int wm = w >> 2, wn = w & 3;
    int row0 = blockIdx.y * 128, colblk = blockIdx.x * 128;

    const __nv_bfloat16* Ahi = (LAYER == 0) ? g_xa_hi : g_fa_hi;
    const __nv_bfloat16* Alo = (LAYER == 0) ? g_xa_lo : g_fa_lo;
    const __nv_bfloat16* Bhi = (LAYER == 0) ? g_w0t_hi : (LAYER == 1) ? g_w1t_hi : g_w2t_hi;
    const __nv_bfloat16* Blo = (LAYER == 0) ? g_w0t_lo : (LAYER == 1) ? g_w1t_lo : g_w2t_lo;

    if (tid < 256) { sals[tid] = 0.f; sald[tid] = 0.f; }

    float acc[4][4][4];
#pragma unroll
    for (int mf = 0; mf < 4; mf++)
#pragma unroll
        for (int nf = 0; nf < 4; nf++)
#pragma unroll
            for (int j = 0; j < 4; j++) acc[mf][nf][j] = 0.f;

    for (int ch = 0; ch < NCH; ch++) {
        int kk = ch * 64;
        __syncthreads();   // protect smem reuse from previous iteration's readers
        // fill: 4 tiles of 128 rows x 64 bf16 (8 chunks of 16B per row)
#pragma unroll
        for (int l = 0; l < 4; l++) {
            int f = tid + 256 * l;
            int r = f >> 3, c = f & 7;
            uint32_t sw = (uint32_t)r * 128 + (((uint32_t)(c ^ (r & 7))) << 4);
            int gr = row0 + r;
            uint4 vh = make_uint4(0, 0, 0, 0), vl = make_uint4(0, 0, 0, 0);
            if (gr < NN) {
                vh = *(const uint4*)(Ahi + (size_t)gr * K + kk + c * 8);
                vl = *(const uint4*)(Alo + (size_t)gr * K + kk + c * 8);
            }
            *(uint4*)(smem + SM_A_HI + sw) = vh;
            *(uint4*)(smem + SM_A_LO + sw) = vl;
            uint4 wh = *(const uint4*)(Bhi + (size_t)(colblk + r) * K + kk + c * 8);
            uint4 wl = *(const uint4*)(Blo + (size_t)(colblk + r) * K + kk + c * 8);
            *(uint4*)(smem + SM_B_HI + sw) = wh;
            *(uint4*)(smem + SM_B_LO + sw) = wl;
        }
        __syncthreads();

#pragma unroll
        for (int s = 0; s < 4; s++) {
            uint32_t ahi[4][4], alo[4][4], bhi[4][2], blo[4][2];
            // A fragments (ldmatrix x4): lanes 0-7 m0, 8-15 m1(+8 rows), 16-23 m2(+16B), 24-31 m3
            int rsel = (lane & 7) + ((lane >> 3) & 1) * 8;
            int kca = 2 * s + (lane >> 4);
#pragma unroll
            for (int mf = 0; mf < 4; mf++) {
                int row = wm * 64 + mf * 16 + rsel;
                uint32_t off = (uint32_t)row * 128 + (((uint32_t)(kca ^ (row & 7))) << 4);
                ldmx4(ahi[mf], sb + SM_A_HI + off);
                ldmx4(alo[mf], sb + SM_A_LO + off);
            }
            // B fragments (ldmatrix x2): lanes 0-7 m0, 8-15 m1(+16B k)
            int le = lane & 15;
            int kcb = 2 * s + (le >> 3);
#pragma unroll
            for (int nf = 0; nf < 4; nf++) {
                int nrow = wn * 32 + nf * 8 + (le & 7);
                uint32_t off = (uint32_t)nrow * 128 + (((uint32_t)(kcb ^ (nrow & 7))) << 4);
                ldmx2(bhi[nf], sb + SM_B_HI + off);
                ldmx2(blo[nf], sb + SM_B_LO + off);
            }
#pragma unroll
            for (int mf = 0; mf < 4; mf++)
#pragma unroll
                for (int nf = 0; nf < 4; nf++) {
                    mma16816(acc[mf][nf], ahi[mf], bhi[nf]);
                    mma16816(acc[mf][nf], ahi[mf], blo[nf]);
                    mma16816(acc[mf][nf], alo[mf], bhi[nf]);
                }
        }
    }

    // epilogue: write C (fp32) + fused al_s/al_d row dots
    int hl = wn >> 1;   // local head (0/1) within the 128-col block
#pragma unroll
    for (int mf = 0; mf < 4; mf++) {
        int lr0 = wm * 64 + mf * 16 + (lane >> 2);   // local row 0..127
        int row_a = row0 + lr0;
        int row_b = row_a + 8;
        float ps0 = 0.f, pd0 = 0.f, ps8 = 0.f, pd8 = 0.f;
#pragma unroll
        for (int nf = 0; nf < 4; nf++) {
            float* c = acc[mf][nf];
            int colg = colblk + wn * 32 + nf * 8 + (lane & 3) * 2;
            if (row_a < NN) *(float2*)(g_h + (size_t)row_a * Nc + colg) = make_float2(c[0], c[1]);
            if (row_b < NN) *(float2*)(g_h + (size_t)row_b * Nc + colg) = make_float2(c[2], c[3]);
            float w0s = asrc[colg], w1s = asrc[colg + 1];
            float w0d = adst[colg], w1d = adst[colg + 1];
            ps0 += c[0] * w0s + c[1] * w1s; pd0 += c[0] * w0d + c[1] * w1d;
            ps8 += c[2] * w0s + c[3] * w1s; pd8 += c[2] * w0d + c[3] * w1d;
        }
#pragma unroll
        for (int off = 1; off <= 2; off <<= 1) {
            ps0 += __shfl_xor_sync(0xffffffffu, ps0, off);
            pd0 += __shfl_xor_sync(0xffffffffu, pd0, off);
            ps8 += __shfl_xor_sync(0xffffffffu, ps8, off);
            pd8 += __shfl_xor_sync(0xffffffffu, pd8, off);
        }
        if ((lane & 3) == 0) {
            atomicAdd(&sals[lr0 * 2 + hl], ps0);
            atomicAdd(&sald[lr0 * 2 + hl], pd0);
            atomicAdd(&sals[(lr0 + 8) * 2 + hl], ps8);
            atomicAdd(&sald[(lr0 + 8) * 2 + hl], pd8);
        }
    }
    __syncthreads();

    if (LAYER == 2) {
        if (tid < 128) {
            int row = row0 + tid;
            if (row < NN) {
                g_als[row] = sals[tid * 2] + sals[tid * 2 + 1];
                g_ald[row] = sald[tid * 2] + sald[tid * 2 + 1];
            }
        }
    } else {
        if (tid < 256) {
            int lr = tid >> 1, h = tid & 1;
            int row = row0 + lr;
            int head = blockIdx.x * 2 + h;
            if (row < NN) {
                g_als[row * 4 + head] = sals[tid];
                g_ald[row * 4 + head] = sald[tid];
            }
        }
    }
}

// ---------------- fused softmax + aggregation + bias (+ELU), warp per dst node ----------------
template <int H, int C, bool ELU, int OUT_MODE>   // OUT_MODE 0: split bf16 feat; 1: fp32 out
__global__ void __launch_bounds__(256) agg_k(
    const float* __restrict__ bias, float* __restrict__ outp)
{
    constexpr int HC = H * C;
    constexpr int V = HC / 128;
    int nd = (blockIdx.x * blockDim.x + threadIdx.x) >> 5;
    int lane = threadIdx.x & 31;
    if (nd >= NN) return;
    int beg = g_rowptr[nd], end = g_rowptr[nd + 1];

    float aldv = (lane < H) ? g_ald[nd * H + lane] : 0.f;

    float4 acc[V];
#pragma unroll
    for (int v = 0; v < V; v++) acc[v] = make_float4(0.f, 0.f, 0.f, 0.f);
    float denom = 0.f;

    for (int e = beg; e < end; e++) {
        int s = g_col[e];
        float exh = 0.f;
        if (lane < H) {
            float ev = g_als[s * H + lane] + aldv;
            ev = ev > 0.f ? ev : 0.2f * ev;
            exh = __expf(ev);
            denom += exh;
        }
        const float4* hv = (const float4*)(g_h + (size_t)s * HC);
#pragma unroll
        for (int v = 0; v < V; v++) {
            int c4 = lane + 32 * v;
            int head = (4 * c4) / C;
            float a = __shfl_sync(0xffffffffu, exh, head);
            float4 xv = hv[c4];
            acc[v].x += a * xv.x;
            acc[v].y += a * xv.y;
            acc[v].z += a * xv.z;
            acc[v].w += a * xv.w;
        }
    }

#pragma unroll
    for (int v = 0; v < V; v++) {
        int c4 = lane + 32 * v;
        int head = (4 * c4) / C;
        float den = __shfl_sync(0xffffffffu, denom, head) + 1e-16f;
        float inv = 1.f / den;
        float4 b4 = ((const float4*)bias)[c4];
        float4 o;
        o.x = acc[v].x * inv + b4.x;
        o.y = acc[v].y * inv + b4.y;
        o.z = acc[v].z * inv + b4.z;
        o.w = acc[v].w * inv + b4.w;
        if (ELU) {
            o.x = o.x > 0.f ? o.x : expm1f(o.x);
            o.y = o.y > 0.f ? o.y : expm1f(o.y);
            o.z = o.z > 0.f ? o.z : expm1f(o.z);
            o.w = o.w > 0.f ? o.w : expm1f(o.w);
        }
        if (OUT_MODE == 1) {
            ((float4*)(outp + (size_t)nd * HC))[c4] = o;
        } else {
            __nv_bfloat16 hx = __float2bfloat16(o.x), hy = __float2bfloat16(o.y);
            __nv_bfloat16 hz = __float2bfloat16(o.z), hw = __float2bfloat16(o.w);
            __nv_bfloat162 h01 = __halves2bfloat162(hx, hy);
            __nv_bfloat162 h23 = __halves2bfloat162(hz, hw);
            uint2 hp;
            hp.x = *(uint32_t*)&h01; hp.y = *(uint32_t*)&h23;
            ((uint2*)(g_fa_hi + (size_t)nd * HC))[c4] = hp;
            __nv_bfloat162 l01 = __halves2bfloat162(
                __float2bfloat16(o.x - __bfloat162float(hx)),
                __float2bfloat16(o.y - __bfloat162float(hy)));
            __nv_bfloat162 l23 = __halves2bfloat162(
                __float2bfloat16(o.z - __bfloat162float(hz)),
                __float2bfloat16(o.w - __bfloat162float(hw)));
            uint2 lp;
            lp.x = *(uint32_t*)&l01; lp.y = *(uint32_t*)&l23;
            ((uint2*)(g_fa_lo + (size_t)nd * HC))[c4] = lp;
        }
    }
}

// ---------------- launch ----------------
extern "C" void kernel_launch(void* const* d_in, const int* in_sizes, int n_in,
                              void* d_out, int out_size)
{
    const float* x   = (const float*)d_in[0];
    const int*   ew  = (const int*)d_in[1];
    const float* W0  = (const float*)d_in[2];
    const float* as0 = (const float*)d_in[3];
    const float* ad0 = (const float*)d_in[4];
    const float* b0  = (const float*)d_in[5];
    const float* W1  = (const float*)d_in[6];
    const float* as1 = (const float*)d_in[7];
    const float* ad1 = (const float*)d_in[8];
    const float* b1  = (const float*)d_in[9];
    const float* W2  = (const float*)d_in[10];
    const float* as2 = (const float*)d_in[11];
    const float* ad2 = (const float*)d_in[12];
    const float* b2  = (const float*)d_in[13];
    float* out = (float*)d_out;

    cudaFuncSetAttribute(mm_k<0>, cudaFuncAttributeMaxDynamicSharedMemorySize, SMEM_MM);
    cudaFuncSetAttribute(mm_k<1>, cudaFuncAttributeMaxDynamicSharedMemorySize, SMEM_MM);
    cudaFuncSetAttribute(mm_k<2>, cudaFuncAttributeMaxDynamicSharedMemorySize, SMEM_MM);

    // CSR build
    detect_k<<<1, 1>>>(ew);
    zero_wp<<<(NN + 256) / 256, 256>>>();
    hist_k<<<(ETOT + 255) / 256, 256>>>(ew);
    part_k<<<SCB, 256>>>();
    bscan_k<<<1, 512>>>();
    final_k<<<SCB, 256>>>();
    scatter_k<<<(ETOT + 255) / 256, 256>>>(ew);

    // weight transpose+split, input split
    prepw_k<<<(NFEAT * HID + 255) / 256, 256>>>(W0, 0, NFEAT, HID);
    prepw_k<<<(HID * HID + 255) / 256, 256>>>(W1, 1, HID, HID);
    prepw_k<<<(HID * NOUTF + 255) / 256, 256>>>(W2, 2, HID, NOUTF);
    prepx_k<<<(NN * NFEAT + 255) / 256, 256>>>(x);

    int warp_blocks = (NN * 32 + 255) / 256;
    int mtiles = (NN + 127) / 128;

    // layer 0
    mm_k<0><<<dim3(2, mtiles), 256, SMEM_MM>>>(as0, ad0);
    agg_k<4, 64, true, 0><<<warp_blocks, 256>>>(b0, nullptr);
    // layer 1
    mm_k<1><<<dim3(2, mtiles), 256, SMEM_MM>>>(as1, ad1);
    agg_k<4, 64, true, 0><<<warp_blocks, 256>>>(b1, nullptr);
    // layer 2
    mm_k<2><<<dim3(1, mtiles), 256, SMEM_MM>>>(as2, ad2);
    agg_k<1, 128, false, 1><<<warp_blocks, 256>>>(b2, out);
}